// round 5
// baseline (speedup 1.0000x reference)
#include <cuda_runtime.h>
#include <math.h>

#define D        32
#define SPLITS   11
#define TT       64
#define BLK      128
#define QT       2
#define QB       (BLK*QT)      // 256 queries per block
#define M_MAX    16384
#define N_MAX    8192
#define EPSV     1e-8f
#define BWB      64

// ---------------- device scratch ----------------
__device__ float        g_cl;                       // c * log2(e)
__device__ float4       g_terr[N_MAX];              // (t2, 1, r, 1)
__device__ double       g_bws [BWB * D];
__device__ double       g_bws2[BWB * D];
__device__ float        g_pnum[SPLITS][M_MAX];
__device__ float        g_pden[SPLITS][M_MAX];
__device__ float        g_rx[M_MAX];
__device__ unsigned int g_rmin, g_rmax, g_smin, g_smax;

// ---------------- helpers ----------------
__device__ __forceinline__ unsigned long long pack2(float lo, float hi) {
    unsigned long long r;
    asm("mov.b64 %0, {%1, %2};" : "=l"(r) : "f"(lo), "f"(hi));
    return r;
}
__device__ __forceinline__ unsigned long long dup2(float v) {
    unsigned long long r;
    asm("mov.b64 %0, {%1, %1};" : "=l"(r) : "f"(v));
    return r;
}
__device__ __forceinline__ unsigned long long fma2(unsigned long long a,
                                                   unsigned long long b,
                                                   unsigned long long c) {
    unsigned long long d;
    asm("fma.rn.f32x2 %0, %1, %2, %3;" : "=l"(d) : "l"(a), "l"(b), "l"(c));
    return d;
}
__device__ __forceinline__ unsigned long long add2(unsigned long long a,
                                                   unsigned long long b) {
    unsigned long long d;
    asm("add.rn.f32x2 %0, %1, %2;" : "=l"(d) : "l"(a), "l"(b));
    return d;
}
__device__ __forceinline__ float2 unpack2(unsigned long long p) {
    float2 f;
    asm("mov.b64 {%0, %1}, %2;" : "=f"(f.x), "=f"(f.y) : "l"(p));
    return f;
}
__device__ __forceinline__ float ex2f(float a) {
    float r;
    asm("ex2.approx.f32 %0, %1;" : "=f"(r) : "f"(a));
    return r;
}
__device__ __forceinline__ void cp16(unsigned int dst_smem, const void* src) {
    asm volatile("cp.async.ca.shared.global [%0], [%1], 16;"
                 :: "r"(dst_smem), "l"(src));
}
__device__ __forceinline__ unsigned int fenc(float f) {
    unsigned int u = __float_as_uint(f);
    return (u & 0x80000000u) ? ~u : (u | 0x80000000u);
}
__device__ __forceinline__ float fdec(unsigned int u) {
    u = (u & 0x80000000u) ? (u & 0x7fffffffu) : ~u;
    return __uint_as_float(u);
}
__device__ __forceinline__ float warp_min(float v) {
    #pragma unroll
    for (int o = 16; o; o >>= 1) v = fminf(v, __shfl_xor_sync(0xffffffffu, v, o));
    return v;
}
__device__ __forceinline__ float warp_max(float v) {
    #pragma unroll
    for (int o = 16; o; o >>= 1) v = fmaxf(v, __shfl_xor_sync(0xffffffffu, v, o));
    return v;
}

// ---------------- bandwidth phase 1 ----------------
__global__ void k_bw1(const float* __restrict__ tx) {
    __shared__ double sds [8][8][4];
    __shared__ double sds2[8][8][4];
    const int tid = threadIdx.x;
    const int b   = blockIdx.x;
    const float4* tx4 = (const float4*)tx;

    double s[4] = {0, 0, 0, 0}, s2[4] = {0, 0, 0, 0};
    #pragma unroll
    for (int it = 0; it < 4; it++) {
        float4 v = tx4[(size_t)(b * 128 + it * 32) * 8 + tid];
        double vx = v.x, vy = v.y, vz = v.z, vw = v.w;
        s[0] += vx; s2[0] += vx * vx;
        s[1] += vy; s2[1] += vy * vy;
        s[2] += vz; s2[2] += vz * vz;
        s[3] += vw; s2[3] += vw * vw;
    }
    #pragma unroll
    for (int o = 8; o <= 16; o <<= 1) {
        #pragma unroll
        for (int k = 0; k < 4; k++) {
            s [k] += __shfl_xor_sync(0xffffffffu, s [k], o);
            s2[k] += __shfl_xor_sync(0xffffffffu, s2[k], o);
        }
    }
    int w = tid >> 5, l = tid & 31;
    if (l < 8) {
        #pragma unroll
        for (int k = 0; k < 4; k++) { sds[w][l][k] = s[k]; sds2[w][l][k] = s2[k]; }
    }
    __syncthreads();
    if (tid < 8) {
        #pragma unroll
        for (int k = 0; k < 4; k++) {
            double a = 0, a2 = 0;
            #pragma unroll
            for (int ww = 0; ww < 8; ww++) { a += sds[ww][tid][k]; a2 += sds2[ww][tid][k]; }
            g_bws [b * D + tid * 4 + k] = a;
            g_bws2[b * D + tid * 4 + k] = a2;
        }
    }
}

// ---------------- bandwidth phase 2 ----------------
__global__ void k_bw2(int n) {
    int d = threadIdx.x;
    double s = 0, s2 = 0;
    for (int b = 0; b < BWB; b++) { s += g_bws[b * D + d]; s2 += g_bws2[b * D + d]; }
    double mean = s / (double)n;
    double var  = (s2 - (double)n * mean * mean) / (double)(n - 1);
    double sd   = sqrt(var > 0.0 ? var : 0.0);
    #pragma unroll
    for (int o = 16; o; o >>= 1) sd += __shfl_xor_sync(0xffffffffu, sd, o);
    if (d == 0) {
        double ms = sd / (double)D;
        double bw = ms * exp(-log((double)n) / (double)(D + 4));
        double c  = 1.0 / (2.0 * bw * bw);
        g_cl = (float)(c * 1.4426950408889634);
        g_rmin = 0xFFFFFFFFu; g_rmax = 0u;
        g_smin = 0xFFFFFFFFu; g_smax = 0u;
    }
}

// ---------------- train extension vectors (independent of bandwidth) ---------
__global__ void k_t2(const float* __restrict__ tx, const float* __restrict__ tr, int n) {
    int j = blockIdx.x * blockDim.x + threadIdx.x;
    if (j >= n) return;
    const float4* r = (const float4*)(tx + (size_t)j * D);
    float s = 0.f;
    #pragma unroll
    for (int k = 0; k < D / 4; k++) {
        float4 v = r[k];
        s = fmaf(v.x, v.x, s); s = fmaf(v.y, v.y, s);
        s = fmaf(v.z, v.z, s); s = fmaf(v.w, v.w, s);
    }
    g_terr[j] = make_float4(s, 1.0f, tr[j], 1.0f);   // raw t2; -cl folded query-side
}

// ---------------- pairwise KDE mainloop ----------------
// 2 queries/thread (q, q+BLK), 128 thr, occ 5 (20 warps/SM). Double-buffered cp.async.
__global__ void __launch_bounds__(BLK, 5)
k_main(const float* __restrict__ x, const float* __restrict__ tx, int m, int n) {
    __shared__ float4 sh_c[2][TT * 8];
    __shared__ float4 sh_e[2][TT];

    const float cl = g_cl;
    const float K2 = cl + cl;
    const int tid = threadIdx.x;
    const int q0  = blockIdx.x * QB + tid;
    const int q1  = q0 + BLK;

    unsigned long long qr0[D / 2 + 1], qr1[D / 2 + 1];
    {
        const float4* p0 = (const float4*)(x + (size_t)q0 * D);
        const float4* p1 = (const float4*)(x + (size_t)q1 * D);
        float q2_0 = 0.f, q2_1 = 0.f;
        #pragma unroll
        for (int k = 0; k < D / 4; k++) {
            float4 a = p0[k], b = p1[k];
            q2_0 = fmaf(a.x, a.x, q2_0); q2_0 = fmaf(a.y, a.y, q2_0);
            q2_0 = fmaf(a.z, a.z, q2_0); q2_0 = fmaf(a.w, a.w, q2_0);
            q2_1 = fmaf(b.x, b.x, q2_1); q2_1 = fmaf(b.y, b.y, q2_1);
            q2_1 = fmaf(b.z, b.z, q2_1); q2_1 = fmaf(b.w, b.w, q2_1);
            qr0[2 * k]     = pack2(a.x * K2, a.y * K2);
            qr0[2 * k + 1] = pack2(a.z * K2, a.w * K2);
            qr1[2 * k]     = pack2(b.x * K2, b.y * K2);
            qr1[2 * k + 1] = pack2(b.z * K2, b.w * K2);
        }
        qr0[D / 2] = pack2(-cl, -cl * q2_0);   // fma with (t2, 1) adds (-cl*t2, -cl*q2)
        qr1[D / 2] = pack2(-cl, -cl * q2_1);
    }

    unsigned long long nd0 = 0ull, nd1 = 0ull;

    const int NT = n / TT;
    const int tb_lo = (blockIdx.y * NT) / SPLITS;
    const int tb_hi = ((blockIdx.y + 1) * NT) / SPLITS;

    unsigned int sc0 = (unsigned int)__cvta_generic_to_shared(&sh_c[0][0]);
    unsigned int sc1 = (unsigned int)__cvta_generic_to_shared(&sh_c[1][0]);
    unsigned int se0 = (unsigned int)__cvta_generic_to_shared(&sh_e[0][0]);
    unsigned int se1 = (unsigned int)__cvta_generic_to_shared(&sh_e[1][0]);

    auto issue = [&](int tb, int buf) {
        const float4* src = ((const float4*)tx) + (size_t)tb * TT * 8;
        unsigned int dc = buf ? sc1 : sc0;
        unsigned int de = buf ? se1 : se0;
        #pragma unroll
        for (int i = 0; i < 4; i++)
            cp16(dc + (tid + i * BLK) * 16, src + tid + i * BLK);
        if (tid < TT) cp16(de + tid * 16, g_terr + (size_t)tb * TT + tid);
        asm volatile("cp.async.commit_group;");
    };

    issue(tb_lo, 0);
    int buf = 0;
    for (int tb = tb_lo; tb < tb_hi; tb++) {
        if (tb + 1 < tb_hi) {
            issue(tb + 1, buf ^ 1);
            asm volatile("cp.async.wait_group 1;");
        } else {
            asm volatile("cp.async.wait_group 0;");
        }
        __syncthreads();

        const ulonglong2* cbase = (const ulonglong2*)(buf ? &sh_c[1][0] : &sh_c[0][0]);
        const ulonglong2* ebase = (const ulonglong2*)(buf ? &sh_e[1][0] : &sh_e[0][0]);

        #pragma unroll 2
        for (int t = 0; t < TT; t++) {
            const ulonglong2* tv = cbase + t * 8;
            unsigned long long a0x = 0ull, a0y = 0ull, a1x = 0ull, a1y = 0ull;
            #pragma unroll
            for (int k = 0; k < 8; k++) {
                ulonglong2 w = tv[k];
                a0x = fma2(qr0[2 * k],     w.x, a0x);
                a0y = fma2(qr0[2 * k + 1], w.y, a0y);
                a1x = fma2(qr1[2 * k],     w.x, a1x);
                a1y = fma2(qr1[2 * k + 1], w.y, a1y);
            }
            ulonglong2 e = ebase[t];
            a0x = fma2(qr0[D / 2], e.x, a0x);
            a1x = fma2(qr1[D / 2], e.x, a1x);
            unsigned long long s0 = add2(a0x, a0y);
            unsigned long long s1 = add2(a1x, a1y);
            float2 f0 = unpack2(s0), f1 = unpack2(s1);
            float w0 = ex2f(f0.x + f0.y);
            float w1 = ex2f(f1.x + f1.y);
            nd0 = fma2(dup2(w0), e.y, nd0);
            nd1 = fma2(dup2(w1), e.y, nd1);
        }
        __syncthreads();
        buf ^= 1;
    }

    float2 r0 = unpack2(nd0), r1 = unpack2(nd1);
    g_pnum[blockIdx.y][q0] = r0.x;
    g_pden[blockIdx.y][q0] = r0.y;
    g_pnum[blockIdx.y][q1] = r1.x;
    g_pden[blockIdx.y][q1] = r1.y;
}

// ---------------- reduce splits -> rx, global min/max ----------------
__global__ void k_reduce(const float* __restrict__ sig, int m) {
    __shared__ float s_rmin[8], s_rmax[8], s_smin[8], s_smax[8];
    int q = blockIdx.x * blockDim.x + threadIdx.x;
    float rx = 3.4e38f, rxmx = -3.4e38f, sg = 3.4e38f, sgmx = -3.4e38f;
    if (q < m) {
        float num = 0.f, den = 0.f;
        #pragma unroll
        for (int s = 0; s < SPLITS; s++) { num += g_pnum[s][q]; den += g_pden[s][q]; }
        float r = num / (den + EPSV);
        g_rx[q] = r;
        rx = r; rxmx = r;
        float sv = sig[q];
        sg = sv; sgmx = sv;
    }
    float wmin_r = warp_min(rx),  wmax_r = warp_max(rxmx);
    float wmin_s = warp_min(sg),  wmax_s = warp_max(sgmx);
    int w = threadIdx.x >> 5, l = threadIdx.x & 31;
    int nw = blockDim.x >> 5;
    if (l == 0) { s_rmin[w] = wmin_r; s_rmax[w] = wmax_r; s_smin[w] = wmin_s; s_smax[w] = wmax_s; }
    __syncthreads();
    if (threadIdx.x == 0) {
        float bmin_r = s_rmin[0], bmax_r = s_rmax[0], bmin_s = s_smin[0], bmax_s = s_smax[0];
        for (int i = 1; i < nw; i++) {
            bmin_r = fminf(bmin_r, s_rmin[i]); bmax_r = fmaxf(bmax_r, s_rmax[i]);
            bmin_s = fminf(bmin_s, s_smin[i]); bmax_s = fmaxf(bmax_s, s_smax[i]);
        }
        atomicMin(&g_rmin, fenc(bmin_r)); atomicMax(&g_rmax, fenc(bmax_r));
        atomicMin(&g_smin, fenc(bmin_s)); atomicMax(&g_smax, fenc(bmax_s));
    }
}

// ---------------- final normalize + combine ----------------
__global__ void k_final(const float* __restrict__ sig, float* __restrict__ out, int m) {
    int q = blockIdx.x * blockDim.x + threadIdx.x;
    if (q >= m) return;
    float rmin = fdec(g_rmin), rmax = fdec(g_rmax);
    float smin = fdec(g_smin), smax = fdec(g_smax);
    float t1 = 0.5f * (g_rx[q] - rmin) / (rmax - rmin + EPSV);
    float t2 = 0.5f * (sig[q]  - smin) / (smax - smin + EPSV);
    out[q] = t1 + t2;
}

// ---------------- launch ----------------
extern "C" void kernel_launch(void* const* d_in, const int* in_sizes, int n_in,
                              void* d_out, int out_size) {
    const float* x   = (const float*)d_in[0];   // [m, 32]
    const float* tx  = (const float*)d_in[1];   // [n, 32]
    const float* tr  = (const float*)d_in[2];   // [n]
    const float* sig = (const float*)d_in[3];   // [m]
    int m = in_sizes[0] / D;   // 16384
    int n = in_sizes[1] / D;   // 8192

    k_t2<<<(n + 255) / 256, 256>>>(tx, tr, n);
    k_bw1<<<BWB, 256>>>(tx);
    k_bw2<<<1, 32>>>(n);
    dim3 grid(m / QB, SPLITS);
    k_main<<<grid, BLK>>>(x, tx, m, n);
    k_reduce<<<(m + 255) / 256, 256>>>(sig, m);
    k_final<<<(m + 255) / 256, 256>>>(sig, (float*)d_out, m);
}